// round 17
// baseline (speedup 1.0000x reference)
#include <cuda_runtime.h>
#include <cuda_bf16.h>

// Problem constants
#define BB 2
#define LL 384
#define EE 512
#define HH 8
#define HD 64
#define BH 16            // BB*HH
#define MROWS 768        // BB*LL
#define CATOMS 16        // HD/4
#define JS 16            // j-splits for parallelism
#define JCHUNK 24        // LL/JS
#define PSZ (BH * LL * HD)   // one partial slot: 393216 floats

// Scratch (no allocations allowed -> device globals)
__device__ float g_q[BH * LL * HD];
__device__ float g_k[BH * LL * HD];
__device__ float g_v[BH * LL * HD];
__device__ float g_part[JS * BH * LL * HD];   // 25 MB, reused by every stage
__device__ float g_ctx[MROWS * EE];

// ---------------------------------------------------------------------------
// Packed f32x2 helpers (sm_103a FFMA2 path — only reachable via PTX)
// ---------------------------------------------------------------------------
typedef unsigned long long u64;

__device__ __forceinline__ u64 pk2(float lo, float hi) {
    u64 r; asm("mov.b64 %0, {%1, %2};" : "=l"(r) : "f"(lo), "f"(hi)); return r;
}
__device__ __forceinline__ float2 upk2(u64 a) {
    float2 f; asm("mov.b64 {%0, %1}, %2;" : "=f"(f.x), "=f"(f.y) : "l"(a)); return f;
}
__device__ __forceinline__ u64 f2fma(u64 a, u64 b, u64 c) {
    u64 r; asm("fma.rn.f32x2 %0, %1, %2, %3;" : "=l"(r) : "l"(a), "l"(b), "l"(c)); return r;
}
__device__ __forceinline__ u64 f2mul(u64 a, u64 b) {
    u64 r; asm("mul.rn.f32x2 %0, %1, %2;" : "=l"(r) : "l"(a), "l"(b)); return r;
}
__device__ __forceinline__ u64 f2add(u64 a, u64 b) {
    u64 r; asm("add.rn.f32x2 %0, %1, %2;" : "=l"(r) : "l"(a), "l"(b)); return r;
}
__device__ __forceinline__ float frsqrt(float x) {
    float r; asm("rsqrt.approx.f32 %0, %1;" : "=f"(r) : "f"(x)); return r;
}
__device__ __forceinline__ float frcp(float x) {
    float r; asm("rcp.approx.f32 %0, %1;" : "=f"(r) : "f"(x)); return r;
}

// ---------------------------------------------------------------------------
// GEMM tile body: 32x64 output tile, 128 threads, 4x4 micro (f32x2),
// double-buffered smem over NT k-tiles of 16. Row stride passed via pointers.
// ---------------------------------------------------------------------------
__device__ __forceinline__ void gemm_tile_body(
    const float* __restrict__ Ap, const float* __restrict__ Bp0,
    const float* __restrict__ Bp1, int NT,
    float As[2][16][32], float Bs[2][16][64],
    int lrow, int lk4, int tx, int ty, u64 acc[4][2])
{
#pragma unroll
    for (int i = 0; i < 4; i++) { acc[i][0] = 0ull; acc[i][1] = 0ull; }

    {
        float4 av = *(const float4*)(Ap);
        float4 b0 = *(const float4*)(Bp0);
        float4 b1 = *(const float4*)(Bp1);
        As[0][lk4+0][lrow] = av.x; As[0][lk4+1][lrow] = av.y;
        As[0][lk4+2][lrow] = av.z; As[0][lk4+3][lrow] = av.w;
        Bs[0][lk4+0][lrow] = b0.x; Bs[0][lk4+1][lrow] = b0.y;
        Bs[0][lk4+2][lrow] = b0.z; Bs[0][lk4+3][lrow] = b0.w;
        Bs[0][lk4+0][lrow+32] = b1.x; Bs[0][lk4+1][lrow+32] = b1.y;
        Bs[0][lk4+2][lrow+32] = b1.z; Bs[0][lk4+3][lrow+32] = b1.w;
    }
    __syncthreads();

    int buf = 0;
    for (int t = 0; t < NT; t++) {
        const bool more = (t + 1) < NT;
        float4 na, nb0, nb1;
        if (more) {
            na  = *(const float4*)(Ap  + (t + 1) * 16);
            nb0 = *(const float4*)(Bp0 + (t + 1) * 16);
            nb1 = *(const float4*)(Bp1 + (t + 1) * 16);
        }
#pragma unroll
        for (int kk = 0; kk < 16; kk++) {
            float4 a4 = *(const float4*)&As[buf][kk][ty << 2];
            ulonglong2 b4 = *(const ulonglong2*)&Bs[buf][kk][tx << 2];
            u64 a0 = pk2(a4.x, a4.x), a1 = pk2(a4.y, a4.y);
            u64 a2 = pk2(a4.z, a4.z), a3 = pk2(a4.w, a4.w);
            acc[0][0] = f2fma(a0, b4.x, acc[0][0]); acc[0][1] = f2fma(a0, b4.y, acc[0][1]);
            acc[1][0] = f2fma(a1, b4.x, acc[1][0]); acc[1][1] = f2fma(a1, b4.y, acc[1][1]);
            acc[2][0] = f2fma(a2, b4.x, acc[2][0]); acc[2][1] = f2fma(a2, b4.y, acc[2][1]);
            acc[3][0] = f2fma(a3, b4.x, acc[3][0]); acc[3][1] = f2fma(a3, b4.y, acc[3][1]);
        }
        if (more) {
            int nb = buf ^ 1;
            As[nb][lk4+0][lrow] = na.x;  As[nb][lk4+1][lrow] = na.y;
            As[nb][lk4+2][lrow] = na.z;  As[nb][lk4+3][lrow] = na.w;
            Bs[nb][lk4+0][lrow] = nb0.x; Bs[nb][lk4+1][lrow] = nb0.y;
            Bs[nb][lk4+2][lrow] = nb0.z; Bs[nb][lk4+3][lrow] = nb0.w;
            Bs[nb][lk4+0][lrow+32] = nb1.x; Bs[nb][lk4+1][lrow+32] = nb1.y;
            Bs[nb][lk4+2][lrow+32] = nb1.z; Bs[nb][lk4+3][lrow+32] = nb1.w;
        }
        __syncthreads();
        buf ^= 1;
    }
}

// ---------------------------------------------------------------------------
// QKV projection with split-K=4. grid (8, 24, 12): z = which*4 + ks.
// ---------------------------------------------------------------------------
__global__ __launch_bounds__(128) void qkv_gemm_kernel(
    const float* __restrict__ x,
    const float* __restrict__ Wq,
    const float* __restrict__ Wk,
    const float* __restrict__ Wv)
{
    __shared__ __align__(16) float As[2][16][32];
    __shared__ __align__(16) float Bs[2][16][64];

    const int which = blockIdx.z >> 2;
    const int ks = blockIdx.z & 3;
    const int kbase = ks << 7;                // 0,128,256,384
    const float* W = (which == 0) ? Wq : (which == 1 ? Wk : Wv);
    float* out = g_part + (size_t)blockIdx.z * PSZ;

    const int m0 = blockIdx.y * 32;
    const int n0 = blockIdx.x * 64;
    const int tid = threadIdx.x;
    const int tx = tid & 15;
    const int ty = tid >> 4;
    const int lrow = tid >> 2;
    const int lk4 = (tid & 3) << 2;

    const float* Ap  = x + (m0 + lrow) * EE + kbase + lk4;
    const float* Bp0 = W + (n0 + lrow) * EE + kbase + lk4;
    const float* Bp1 = W + (n0 + lrow + 32) * EE + kbase + lk4;

    u64 acc[4][2];
    gemm_tile_body(Ap, Bp0, Bp1, 8, As, Bs, lrow, lk4, tx, ty, acc);

    const int b = m0 / LL;
    const int h = n0 >> 6;
    const int lbase = m0 - b * LL;
#pragma unroll
    for (int i = 0; i < 4; i++) {
        float2 lo = upk2(acc[i][0]);
        float2 hi = upk2(acc[i][1]);
        int l = lbase + (ty << 2) + i;
        *(float4*)(out + (((b << 3) + h) * LL + l) * HD + (tx << 2)) =
            make_float4(lo.x, lo.y, hi.x, hi.y);
    }
}

// Sum the 4 split-K partials into g_q/g_k/g_v.
// For Q and K, also normalize each quaternion atom: |hamilton(q,k)|=|q||k|,
// so pre-normalizing q,k makes the interference spinor unit-norm by
// construction — the O(L^2) normalization vanishes.
__global__ __launch_bounds__(256) void qkv_sum_kernel()
{
    int i = blockIdx.x * 256 + threadIdx.x;          // over PSZ/4 float4s
    int which = blockIdx.y;
    float4* dst = (float4*)((which == 0) ? g_q : (which == 1 ? g_k : g_v));
    const float4* p0 = (const float4*)(g_part + (size_t)(which * 4 + 0) * PSZ);
    const float4* p1 = (const float4*)(g_part + (size_t)(which * 4 + 1) * PSZ);
    const float4* p2 = (const float4*)(g_part + (size_t)(which * 4 + 2) * PSZ);
    const float4* p3 = (const float4*)(g_part + (size_t)(which * 4 + 3) * PSZ);
    float4 a = p0[i], b = p1[i], c = p2[i], d = p3[i];
    float4 s = make_float4(a.x + b.x + c.x + d.x, a.y + b.y + c.y + d.y,
                           a.z + b.z + c.z + d.z, a.w + b.w + c.w + d.w);
    if (which < 2) {
        float n2 = s.x * s.x + s.y * s.y + s.z * s.z + s.w * s.w;
        float r = frsqrt(n2 + 1e-32f);
        s.x *= r; s.y *= r; s.z *= r; s.w *= r;
    }
    dst[i] = s;
}

// ---------------------------------------------------------------------------
// Quaternion attention, f32x2-packed. grid = (6, 16, JS), block = 128.
// q,k pre-normalized -> Hamilton(q,k) is the unit spinor directly.
// K and V staged 7-component (w,x,y,z,-x,-y,-z); all Hamilton signs come
// from operand selection. K/V comps fetched as LDS.128 (ulonglong2 = two
// atom-pairs at once) — halves the LDS instruction count in the hot loop.
// ---------------------------------------------------------------------------
__global__ __launch_bounds__(128) void attn_kernel(
    const float* __restrict__ dde_w,
    const float* __restrict__ dde_b)
{
    __shared__ __align__(16) u64 sk[JCHUNK][7][8];
    __shared__ __align__(16) u64 sv[JCHUNK][7][8];
    __shared__ float swp[16];          // dde_w / 16 (mean folded in)
    __shared__ float sbp[4];

    const int tid = threadIdx.x;
    const int rb = blockIdx.x;
    const int bh = blockIdx.y;
    const int js = blockIdx.z;
    const int j0 = js * JCHUNK;

    if (tid < 16) swp[tid] = __ldg(&dde_w[tid]) * (1.0f / 16.0f);
    if (tid < 4)  sbp[tid] = __ldg(&dde_b[tid]);

    const float4* kg = (const float4*)(g_k + (bh * LL + j0) * HD);
    const float4* vg = (const float4*)(g_v + (bh * LL + j0) * HD);
    float* skf = (float*)sk;
    float* svf = (float*)sv;
    for (int t = tid; t < JCHUNK * CATOMS; t += 128) {
        int j = t >> 4, a = t & 15, ap = a >> 1, lane = a & 1;
        float4 kq = kg[t];
        float4 vq = vg[t];
        int kb = j * 7 * 16;
        skf[kb + (0*8 + ap)*2 + lane] =  kq.x;
        skf[kb + (1*8 + ap)*2 + lane] =  kq.y;
        skf[kb + (2*8 + ap)*2 + lane] =  kq.z;
        skf[kb + (3*8 + ap)*2 + lane] =  kq.w;
        skf[kb + (4*8 + ap)*2 + lane] = -kq.y;
        skf[kb + (5*8 + ap)*2 + lane] = -kq.z;
        skf[kb + (6*8 + ap)*2 + lane] = -kq.w;
        svf[kb + (0*8 + ap)*2 + lane] =  vq.x;
        svf[kb + (1*8 + ap)*2 + lane] =  vq.y;
        svf[kb + (2*8 + ap)*2 + lane] =  vq.z;
        svf[kb + (3*8 + ap)*2 + lane] =  vq.w;
        svf[kb + (4*8 + ap)*2 + lane] = -vq.y;
        svf[kb + (5*8 + ap)*2 + lane] = -vq.z;
        svf[kb + (6*8 + ap)*2 + lane] = -vq.w;
    }

    const int row = rb * 64 + (tid >> 1);
    const int half = tid & 1;

    const float4* qg = (const float4*)(g_q + (bh * LL + row) * HD);
    u64 qw[4], qx[4], qy[4], qz[4];
#pragma unroll
    for (int p = 0; p < 4; p++) {
        float4 q0 = qg[half * 8 + 2 * p];
        float4 q1 = qg[half * 8 + 2 * p + 1];
        qw[p] = pk2(q0.x, q1.x);
        qx[p] = pk2(q0.y, q1.y);
        qy[p] = pk2(q0.z, q1.z);
        qz[p] = pk2(q0.w, q1.w);
    }

    u64 cw[4], cx[4], cy[4], cz[4];
#pragma unroll
    for (int p = 0; p < 4; p++) { cw[p] = 0ull; cx[p] = 0ull; cy[p] = 0ull; cz[p] = 0ull; }

    __syncthreads();

#pragma unroll 2
    for (int jj = 0; jj < JCHUNK; jj++) {
        u64 sW[4], sX[4], sY[4], sZ[4];
        u64 gw = 0ull, gx = 0ull, gy = 0ull, gz = 0ull;
        // Base for this thread's half: comp c pair-group g at ulonglong2
        // index c*4 + g (two atom-pairs per 16B load).
        const ulonglong2* kb2 = (const ulonglong2*)&sk[jj][0][half * 4];
#pragma unroll
        for (int g = 0; g < 2; g++) {
            ulonglong2 KW = kb2[0*4 + g], KX = kb2[1*4 + g];
            ulonglong2 KY = kb2[2*4 + g], KZ = kb2[3*4 + g];
            ulonglong2 NKX = kb2[4*4 + g], NKY = kb2[5*4 + g], NKZ = kb2[6*4 + g];
#pragma unroll
            for (int s = 0; s < 2; s++) {
                const int p = 2 * g + s;
                u64 kw_ = s ? KW.y : KW.x,  kx_ = s ? KX.y : KX.x;
                u64 ky_ = s ? KY.y : KY.x,  kz_ = s ? KZ.y : KZ.x;
                u64 nkx = s ? NKX.y : NKX.x, nky = s ? NKY.y : NKY.x;
                u64 nkz = s ? NKZ.y : NKZ.x;
                // Hamilton(q, k) on pre-normalized atoms == unit spinor
                u64 hw = f2fma(qz[p], nkz, f2fma(qy[p], nky, f2fma(qx[p], nkx, f2mul(qw[p], kw_))));
                u64 hx = f2fma(qz[p], nky, f2fma(qy[p], kz_, f2fma(qx[p], kw_, f2mul(qw[p], kx_))));
                u64 hy = f2fma(qz[p], kx_, f2fma(qy[p], kw_, f2fma(qx[p], nkz, f2mul(qw[p], ky_))));
                u64 hz = f2fma(qz[p], kw_, f2fma(qy[p], nkx, f2fma(qx[p], ky_, f2mul(qw[p], kz_))));
                sW[p] = hw; sX[p] = hx; sY[p] = hy; sZ[p] = hz;
                gw = f2add(gw, hw); gx = f2add(gx, hx);
                gy = f2add(gy, hy); gz = f2add(gz, hz);
            }
        }
        float2 t0 = upk2(gw), t1 = upk2(gx), t2 = upk2(gy), t3 = upk2(gz);
        float g0 = t0.x + t0.y, g1 = t1.x + t1.y;
        float g2 = t2.x + t2.y, g3 = t3.x + t3.y;
        g0 += __shfl_xor_sync(0xffffffffu, g0, 1);
        g1 += __shfl_xor_sync(0xffffffffu, g1, 1);
        g2 += __shfl_xor_sync(0xffffffffu, g2, 1);
        g3 += __shfl_xor_sync(0xffffffffu, g3, 1);

        float gate[4];
#pragma unroll
        for (int pp = 0; pp < 4; pp++) {
            float z = swp[pp*4+0] * g0 + swp[pp*4+1] * g1 +
                      swp[pp*4+2] * g2 + swp[pp*4+3] * g3 + sbp[pp];
            gate[pp] = frcp(1.0f + __expf(-z));
        }
        u64 G0 = pk2(gate[0], gate[0]), G1 = pk2(gate[1], gate[1]);
        u64 G2 = pk2(gate[2], gate[2]), G3 = pk2(gate[3], gate[3]);

        const ulonglong2* vb2 = (const ulonglong2*)&sv[jj][0][half * 4];
#pragma unroll
        for (int g = 0; g < 2; g++) {
            ulonglong2 VW = vb2[0*4 + g], VX = vb2[1*4 + g];
            ulonglong2 VY = vb2[2*4 + g], VZ = vb2[3*4 + g];
            ulonglong2 NVX = vb2[4*4 + g], NVY = vb2[5*4 + g], NVZ = vb2[6*4 + g];
#pragma unroll
            for (int s = 0; s < 2; s++) {
                const int p = 2 * g + s;
                u64 vw_ = s ? VW.y : VW.x,  vx_ = s ? VX.y : VX.x;
                u64 vy_ = s ? VY.y : VY.x,  vz_ = s ? VZ.y : VZ.x;
                u64 nvx = s ? NVX.y : NVX.x, nvy = s ? NVY.y : NVY.x;
                u64 nvz = s ? NVZ.y : NVZ.x;
                u64 aw = f2mul(sW[p], G0);
                u64 ax = f2mul(sX[p], G1);
                u64 ay = f2mul(sY[p], G2);
                u64 az = f2mul(sZ[p], G3);
                // ctx += Hamilton(a, v); negatives via pre-negated V comps
                cw[p] = f2fma(az, nvz, f2fma(ay, nvy, f2fma(ax, nvx, f2fma(aw, vw_, cw[p]))));
                cx[p] = f2fma(az, nvy, f2fma(ay, vz_, f2fma(ax, vw_, f2fma(aw, vx_, cx[p]))));
                cy[p] = f2fma(az, vx_, f2fma(ay, vw_, f2fma(ax, nvz, f2fma(aw, vy_, cy[p]))));
                cz[p] = f2fma(az, vw_, f2fma(ay, nvx, f2fma(ax, vy_, f2fma(aw, vz_, cz[p]))));
            }
        }
    }

    // Store partials directly in (js, m, e) layout -> linear reduce.
    const int b = bh >> 3;
    const int h = bh & 7;
    float4* pg = (float4*)(g_part + (size_t)js * PSZ +
                           ((size_t)(b * LL + row)) * EE + h * HD);
#pragma unroll
    for (int p = 0; p < 4; p++) {
        float2 w2 = upk2(cw[p]), x2 = upk2(cx[p]);
        float2 y2 = upk2(cy[p]), z2 = upk2(cz[p]);
        pg[half * 8 + 2 * p]     = make_float4(w2.x, x2.x, y2.x, z2.x);
        pg[half * 8 + 2 * p + 1] = make_float4(w2.y, x2.y, y2.y, z2.y);
    }
}

// ---------------------------------------------------------------------------
// Reduce JS partials (linear layout). Two float4 streams per thread for
// 2x memory-level parallelism (kernel is latency-bound, issue=5.4%).
// grid = 192, block = 256: thread i handles float4s 2i and 2i+1.
// ---------------------------------------------------------------------------
__global__ __launch_bounds__(256) void reduce_kernel()
{
    int i = (blockIdx.x * 256 + threadIdx.x) << 1;   // over 98304 float4s
    float4 acc0 = make_float4(0.f, 0.f, 0.f, 0.f);
    float4 acc1 = make_float4(0.f, 0.f, 0.f, 0.f);
#pragma unroll
    for (int js = 0; js < JS; js++) {
        const float4* p = (const float4*)(g_part + (size_t)js * PSZ);
        float4 a = p[i], b = p[i + 1];
        acc0.x += a.x; acc0.y += a.y; acc0.z += a.z; acc0.w += a.w;
        acc1.x += b.x; acc1.y += b.y; acc1.z += b.z; acc1.w += b.w;
    }
    ((float4*)g_ctx)[i] = acc0;
    ((float4*)g_ctx)[i + 1] = acc1;
}

// ---------------------------------------------------------------------------
// Output projection with split-K=4. grid (8, 24, 4).
// ---------------------------------------------------------------------------
__global__ __launch_bounds__(128) void out_gemm_kernel(
    const float* __restrict__ Wo)
{
    __shared__ __align__(16) float As[2][16][32];
    __shared__ __align__(16) float Bs[2][16][64];

    const int ks = blockIdx.z;
    const int kbase = ks << 7;
    float* out = g_part + (size_t)ks * PSZ;

    const int m0 = blockIdx.y * 32;
    const int n0 = blockIdx.x * 64;
    const int tid = threadIdx.x;
    const int tx = tid & 15;
    const int ty = tid >> 4;
    const int lrow = tid >> 2;
    const int lk4 = (tid & 3) << 2;

    const float* Ap  = g_ctx + (m0 + lrow) * EE + kbase + lk4;
    const float* Bp0 = Wo + (n0 + lrow) * EE + kbase + lk4;
    const float* Bp1 = Wo + (n0 + lrow + 32) * EE + kbase + lk4;

    u64 acc[4][2];
    gemm_tile_body(Ap, Bp0, Bp1, 8, As, Bs, lrow, lk4, tx, ty, acc);

#pragma unroll
    for (int i = 0; i < 4; i++) {
        float2 lo = upk2(acc[i][0]);
        float2 hi = upk2(acc[i][1]);
        int m = m0 + (ty << 2) + i;
        *(float4*)(out + m * EE + n0 + (tx << 2)) =
            make_float4(lo.x, lo.y, hi.x, hi.y);
    }
}

// Sum the 4 split-K partials into the final output. grid 384, 256 threads.
__global__ __launch_bounds__(256) void out_sum_kernel(float* __restrict__ out)
{
    int i = blockIdx.x * 256 + threadIdx.x;          // over PSZ/4 float4s
    const float4* p0 = (const float4*)(g_part);
    const float4* p1 = (const float4*)(g_part + (size_t)PSZ);
    const float4* p2 = (const float4*)(g_part + (size_t)2 * PSZ);
    const float4* p3 = (const float4*)(g_part + (size_t)3 * PSZ);
    float4 a = p0[i], b = p1[i], c = p2[i], d = p3[i];
    ((float4*)out)[i] = make_float4(a.x + b.x + c.x + d.x,
                                    a.y + b.y + c.y + d.y,
                                    a.z + b.z + c.z + d.z,
                                    a.w + b.w + c.w + d.w);
}

// ---------------------------------------------------------------------------
extern "C" void kernel_launch(void* const* d_in, const int* in_sizes, int n_in,
                              void* d_out, int out_size)
{
    const float* x     = (const float*)d_in[0];
    const float* Wq    = (const float*)d_in[1];
    const float* Wk    = (const float*)d_in[2];
    const float* Wv    = (const float*)d_in[3];
    const float* Wo    = (const float*)d_in[4];
    const float* dde_w = (const float*)d_in[5];
    const float* dde_b = (const float*)d_in[6];
    float* out = (float*)d_out;

    qkv_gemm_kernel<<<dim3(8, 24, 12), 128>>>(x, Wq, Wk, Wv);
    qkv_sum_kernel<<<dim3(384, 3), 256>>>();
    attn_kernel<<<dim3(6, BH, JS), 128>>>(dde_w, dde_b);
    reduce_kernel<<<192, 256>>>();
    out_gemm_kernel<<<dim3(8, 24, 4), 128>>>(Wo);
    out_sum_kernel<<<384, 256>>>(out);
}